// round 6
// baseline (speedup 1.0000x reference)
#include <cuda_runtime.h>
#include <cuda_fp16.h>
#include <cstdint>

#define QDIM 4096   // q_dim (output rows i)
#define NDIM 4096   // contraction of GEMM1 (n)
#define MDIM 8192   // softmax dim / contraction of GEMM2 (j)
#define VDIM 4096   // v_dim (output cols v)

// ---------------- scratch (static device globals) ---------------------------
__device__ __half g_Qt[(size_t)QDIM * NDIM];   // Qt[i][n] = Q[n][i]
__device__ __half g_Kt[(size_t)MDIM * NDIM];   // Kt[j][n] = K[n][j]
__device__ __half g_Vc[(size_t)VDIM * MDIM];   // Vc[v][j] = V[v][j]
__device__ __half g_P [(size_t)QDIM * MDIM];   // exp(s) UNNORMALIZED fp16
__device__ float  g_rinv[QDIM];                // 1 / row sums

// ---------------- helpers ----------------------------------------------------
__device__ __forceinline__ uint32_t smem_u32(const void* p) {
    uint32_t a;
    asm("{ .reg .u64 t; cvta.to.shared.u64 t, %1; cvt.u32.u64 %0, t; }" : "=r"(a) : "l"(p));
    return a;
}
__device__ __forceinline__ void cp16(uint32_t dst, const void* src) {
    asm volatile("cp.async.cg.shared.global [%0], [%1], 16;" :: "r"(dst), "l"(src));
}
__device__ __forceinline__ void ldsm4(uint32_t* r, uint32_t addr) {
    asm volatile("ldmatrix.sync.aligned.m8n8.x4.shared.b16 {%0,%1,%2,%3}, [%4];"
                 : "=r"(r[0]), "=r"(r[1]), "=r"(r[2]), "=r"(r[3]) : "r"(addr));
}
__device__ __forceinline__ void mma16816(float* d, const uint32_t* a, uint32_t b0, uint32_t b1) {
    asm volatile(
        "mma.sync.aligned.m16n8k16.row.col.f32.f16.f16.f32 "
        "{%0,%1,%2,%3}, {%4,%5,%6,%7}, {%8,%9}, {%0,%1,%2,%3};"
        : "+f"(d[0]), "+f"(d[1]), "+f"(d[2]), "+f"(d[3])
        : "r"(a[0]), "r"(a[1]), "r"(a[2]), "r"(a[3]), "r"(b0), "r"(b1));
}

// ---------------- preprocessing (R3 known-good versions) ----------------------
__global__ void transpose_f2h(const float* __restrict__ in, __half* __restrict__ out,
                              int rows, int cols) {
    __shared__ float tile[32][33];
    int c0 = blockIdx.x * 32, r0 = blockIdx.y * 32;
    int tx = threadIdx.x, ty = threadIdx.y;
    #pragma unroll
    for (int i = ty; i < 32; i += 8)
        tile[i][tx] = in[(size_t)(r0 + i) * cols + (c0 + tx)];
    __syncthreads();
    #pragma unroll
    for (int i = ty; i < 32; i += 8)
        out[(size_t)(c0 + i) * rows + (r0 + tx)] = __float2half(tile[tx][i]);
}

__global__ void convert_f2h(const float* __restrict__ in, __half* __restrict__ out, size_t n) {
    size_t i = ((size_t)blockIdx.x * blockDim.x + threadIdx.x) * 4;
    if (i + 3 < n) {
        float4 v = *reinterpret_cast<const float4*>(in + i);
        *reinterpret_cast<__half2*>(out + i)     = __floats2half2_rn(v.x, v.y);
        *reinterpret_cast<__half2*>(out + i + 2) = __floats2half2_rn(v.z, v.w);
    }
}

// ---------------- mma.sync GEMM: C[M,N] = A[M,K] @ B[N,K]^T  ------------------
// 256 threads, 1 CTA/SM, tile 128x256, warp tile 64x64 (2x4 warps), BK=64,
// 3-stage cp.async, k16-level register double-buffering of fragments.
// EPI=0: C = exp(scale*acc) fp16 ; EPI=1: C = acc * rinv[row] fp32
#define BM 128
#define BN 256
#define BKC 64
#define STAGES 3
#define STG_BYTES ((BM + BN) * 128)          // 48 KB per stage (A then B)
#define SMEM_SZ (STAGES * STG_BYTES)         // 144 KB

template <int EPI>
__global__ __launch_bounds__(256, 1)
void gemm_mma(const __half* __restrict__ A, const __half* __restrict__ B,
              void* __restrict__ Cv, int M, int N, int K,
              const float* __restrict__ rinv) {
    extern __shared__ char smem[];
    const uint32_t sb = smem_u32(smem);
    const int tid = threadIdx.x;
    const int wid = tid >> 5;
    const int lane = tid & 31;
    const int wm = wid & 1;           // 2 warps over M -> 64 rows each
    const int wn = wid >> 1;          // 4 warps over N -> 64 cols each
    const size_t m0 = (size_t)blockIdx.y * BM;
    const size_t n0 = (size_t)blockIdx.x * BN;
    const int nk = K / BKC;

    // cp.async mapping: 8 x 16B chunks per 128B row; 256 threads cover 32 rows/pass
    const int ldrow = tid >> 3;          // 0..31
    const int ldc16 = tid & 7;
    const uint32_t swz_st = ((uint32_t)ldc16 ^ ((uint32_t)ldrow & 7)) << 4;

    auto load_stage = [&](int c, int buf) {
        const uint32_t abase = sb + buf * STG_BYTES;
        const uint32_t bbase = abase + BM * 128;
        const size_t k0 = (size_t)c * BKC;
        #pragma unroll
        for (int i = 0; i < 4; i++) {
            int row = ldrow + i * 32;
            cp16(abase + row * 128 + swz_st, A + (m0 + row) * (size_t)K + k0 + ldc16 * 8);
        }
        #pragma unroll
        for (int i = 0; i < 8; i++) {
            int row = ldrow + i * 32;
            cp16(bbase + row * 128 + swz_st, B + (n0 + row) * (size_t)K + k0 + ldc16 * 8);
        }
        asm volatile("cp.async.commit_group;" ::: "memory");
    };

    float acc[4][8][4];
    #pragma unroll
    for (int i = 0; i < 4; i++)
        #pragma unroll
        for (int j = 0; j < 8; j++)
            #pragma unroll
            for (int r = 0; r < 4; r++) acc[i][j][r] = 0.0f;

    #pragma unroll
    for (int s = 0; s < STAGES - 1; s++) load_stage(s, s);

    // ldmatrix lane addressing
    const uint32_t lrow = lane & 15;
    const uint32_t lhalf = lane >> 4;
    const uint32_t lswz = lane & 7;
    const uint32_t a_rowbyte = (wm * 64 + lrow) * 128;
    const uint32_t b_rowbyte = (wn * 64 + lrow) * 128;
    uint32_t coff[4];
    #pragma unroll
    for (int k16 = 0; k16 < 4; k16++)
        coff[k16] = (((uint32_t)k16 * 2 + lhalf) ^ lswz) << 4;

    // double-buffered register fragments
    uint32_t af[2][4][4], bf[2][4][4];

    for (int it = 0; it < nk; it++) {
        if (it + 1 < nk) asm volatile("cp.async.wait_group 1;" ::: "memory");
        else             asm volatile("cp.async.wait_group 0;" ::: "memory");
        __syncthreads();
        if (it + STAGES - 1 < nk) load_stage(it + STAGES - 1, (it + STAGES - 1) % STAGES);

        const uint32_t abase = sb + (it % STAGES) * STG_BYTES;
        const uint32_t bbase = abase + BM * 128;

        // prime step 0 fragments
        #pragma unroll
        for (int mi = 0; mi < 4; mi++)
            ldsm4(af[0][mi], abase + a_rowbyte + mi * 2048 + coff[0]);
        #pragma unroll
        for (int ni = 0; ni < 4; ni++)
            ldsm4(bf[0][ni], bbase + b_rowbyte + ni * 2048 + coff[0]);

        #pragma unroll
        for (int k16 = 0; k16 < 4; k16++) {
            const int cur = k16 & 1;
            if (k16 < 3) {                 // prefetch next step's fragments
                const int nxt = cur ^ 1;
                #pragma unroll
                for (int mi = 0; mi < 4; mi++)
                    ldsm4(af[nxt][mi], abase + a_rowbyte + mi * 2048 + coff[k16 + 1]);
                #pragma unroll
                for (int ni = 0; ni < 4; ni++)
                    ldsm4(bf[nxt][ni], bbase + b_rowbyte + ni * 2048 + coff[k16 + 1]);
            }
            #pragma unroll
            for (int mi = 0; mi < 4; mi++)
                #pragma unroll
                for (int nj = 0; nj < 8; nj++)
                    mma16816(acc[mi][nj], af[cur][mi],
                             bf[cur][nj >> 1][nj & 1], bf[cur][nj >> 1][(nj & 1) + 2]);
        }
        // single barrier per iter (3 stages: top barrier protects buffer reuse)
    }

    // ---- epilogue -----------------------------------------------------------
    const float scale = 0.015625f;     // 1/sqrt(4096)
    #pragma unroll
    for (int mi = 0; mi < 4; mi++) {
        const size_t r0 = m0 + wm * 64 + mi * 16 + (lane >> 2);
        const size_t r1 = r0 + 8;
        float i0 = 0.f, i1 = 0.f;
        if (EPI == 1) { i0 = rinv[r0]; i1 = rinv[r1]; }
        #pragma unroll
        for (int nj = 0; nj < 8; nj++) {
            const size_t col = n0 + wn * 64 + nj * 8 + (lane & 3) * 2;
            float* c = acc[mi][nj];
            if (EPI == 0) {
                __half* C = (__half*)Cv;
                *reinterpret_cast<__half2*>(&C[r0 * (size_t)N + col]) =
                    __floats2half2_rn(__expf(c[0] * scale), __expf(c[1] * scale));
                *reinterpret_cast<__half2*>(&C[r1 * (size_t)N + col]) =
                    __floats2half2_rn(__expf(c[2] * scale), __expf(c[3] * scale));
            } else {
                float* C = (float*)Cv;
                *reinterpret_cast<float2*>(&C[r0 * (size_t)N + col]) =
                    make_float2(c[0] * i0, c[1] * i0);
                *reinterpret_cast<float2*>(&C[r1 * (size_t)N + col]) =
                    make_float2(c[2] * i1, c[3] * i1);
            }
        }
    }
}

// ---------------- row sums of P -> reciprocal --------------------------------
__global__ __launch_bounds__(256)
void rowsum_recip(const __half* __restrict__ P, float* __restrict__ rinv, int cols) {
    __shared__ float red[256];
    const int row = blockIdx.x;
    const int tid = threadIdx.x;
    const __half2* p = reinterpret_cast<const __half2*>(P + (size_t)row * cols);
    float s = 0.0f;
    for (int j = tid; j < cols / 2; j += 256) {
        float2 v = __half22float2(p[j]);
        s += v.x + v.y;
    }
    red[tid] = s;
    __syncthreads();
    #pragma unroll
    for (int st = 128; st > 0; st >>= 1) {
        if (tid < st) red[tid] += red[tid + st];
        __syncthreads();
    }
    if (tid == 0) rinv[row] = 1.0f / red[0];
}

// ---------------- launch ------------------------------------------------------
extern "C" void kernel_launch(void* const* d_in, const int* in_sizes, int n_in,
                              void* d_out, int out_size) {
    const float* q = (const float*)d_in[0];   // (4096, 4096)  Q[n][i]
    const float* k = (const float*)d_in[1];   // (4096, 8192)  K[n][j]
    const float* v = (const float*)d_in[2];   // (4096, 8192)  V[v][j]
    float* out = (float*)d_out;               // (4096, 4096)  out[i][v]

    __half *pQt, *pKt, *pVc, *pP;
    float* pRinv;
    cudaGetSymbolAddress((void**)&pQt,   g_Qt);
    cudaGetSymbolAddress((void**)&pKt,   g_Kt);
    cudaGetSymbolAddress((void**)&pVc,   g_Vc);
    cudaGetSymbolAddress((void**)&pP,    g_P);
    cudaGetSymbolAddress((void**)&pRinv, g_rinv);

    cudaFuncSetAttribute(gemm_mma<0>, cudaFuncAttributeMaxDynamicSharedMemorySize, SMEM_SZ);
    cudaFuncSetAttribute(gemm_mma<1>, cudaFuncAttributeMaxDynamicSharedMemorySize, SMEM_SZ);

    dim3 tb(32, 8);
    // Qt[i][n] = Q[n][i]
    transpose_f2h<<<dim3(QDIM / 32, NDIM / 32), tb>>>(q, pQt, NDIM, QDIM);
    // Kt[j][n] = K[n][j]
    transpose_f2h<<<dim3(MDIM / 32, NDIM / 32), tb>>>(k, pKt, NDIM, MDIM);
    // Vc straight convert
    {
        size_t n = (size_t)VDIM * MDIM;
        convert_f2h<<<(unsigned)(n / 4 / 256), 256>>>(v, pVc, n);
    }

    // GEMM1 + fused exp: P[i][j] = exp(scale * sum_n Qt[i][n] Kt[j][n])
    gemm_mma<0><<<dim3(MDIM / BN, QDIM / BM), 256, SMEM_SZ>>>(
        pQt, pKt, pP, QDIM, MDIM, NDIM, nullptr);

    // row sums -> reciprocals
    rowsum_recip<<<QDIM, 256>>>(pP, pRinv, MDIM);

    // GEMM2 + fused normalize: out[i][v] = rinv[i] * sum_j P[i][j] Vc[v][j]
    gemm_mma<1><<<dim3(VDIM / BN, QDIM / BM), 256, SMEM_SZ>>>(
        pP, pVc, out, QDIM, VDIM, MDIM, pRinv);
}

// round 7
// speedup vs baseline: 1.0572x; 1.0572x over previous
#include <cuda_runtime.h>
#include <cuda_fp16.h>
#include <cstdint>

#define QDIM 4096   // q_dim (output rows i)
#define NDIM 4096   // contraction of GEMM1 (n)
#define MDIM 8192   // softmax dim / contraction of GEMM2 (j)
#define VDIM 4096   // v_dim (output cols v)

// ---------------- scratch (static device globals) ---------------------------
__device__ __half g_Qt[(size_t)QDIM * NDIM];   // Qt[i][n] = Q[n][i]
__device__ __half g_Kt[(size_t)MDIM * NDIM];   // Kt[j][n] = K[n][j]
__device__ __half g_Vc[(size_t)VDIM * MDIM];   // Vc[v][j] = V[v][j]
__device__ __half g_P [(size_t)QDIM * MDIM];   // exp(s) UNNORMALIZED fp16
__device__ float  g_rinv[QDIM];                // 1 / row sums

// ---------------- helpers ----------------------------------------------------
__device__ __forceinline__ uint32_t smem_u32(const void* p) {
    uint32_t a;
    asm("{ .reg .u64 t; cvta.to.shared.u64 t, %1; cvt.u32.u64 %0, t; }" : "=r"(a) : "l"(p));
    return a;
}
__device__ __forceinline__ void cp16(uint32_t dst, const void* src) {
    asm volatile("cp.async.cg.shared.global [%0], [%1], 16;" :: "r"(dst), "l"(src));
}
__device__ __forceinline__ void ldsm4(uint32_t& r0, uint32_t& r1, uint32_t& r2, uint32_t& r3,
                                      uint32_t addr) {
    asm volatile("ldmatrix.sync.aligned.m8n8.x4.shared.b16 {%0,%1,%2,%3}, [%4];"
                 : "=r"(r0), "=r"(r1), "=r"(r2), "=r"(r3) : "r"(addr));
}
__device__ __forceinline__ void mma16816(float* d, uint32_t a0, uint32_t a1, uint32_t a2,
                                         uint32_t a3, uint32_t b0, uint32_t b1) {
    asm volatile(
        "mma.sync.aligned.m16n8k16.row.col.f32.f16.f16.f32 "
        "{%0,%1,%2,%3}, {%4,%5,%6,%7}, {%8,%9}, {%0,%1,%2,%3};"
        : "+f"(d[0]), "+f"(d[1]), "+f"(d[2]), "+f"(d[3])
        : "r"(a0), "r"(a1), "r"(a2), "r"(a3), "r"(b0), "r"(b1));
}

// ---------------- preprocessing (R3 known-good versions) ----------------------
__global__ void transpose_f2h(const float* __restrict__ in, __half* __restrict__ out,
                              int rows, int cols) {
    __shared__ float tile[32][33];
    int c0 = blockIdx.x * 32, r0 = blockIdx.y * 32;
    int tx = threadIdx.x, ty = threadIdx.y;
    #pragma unroll
    for (int i = ty; i < 32; i += 8)
        tile[i][tx] = in[(size_t)(r0 + i) * cols + (c0 + tx)];
    __syncthreads();
    #pragma unroll
    for (int i = ty; i < 32; i += 8)
        out[(size_t)(c0 + i) * rows + (r0 + tx)] = __float2half(tile[tx][i]);
}

__global__ void convert_f2h(const float* __restrict__ in, __half* __restrict__ out, size_t n) {
    size_t i = ((size_t)blockIdx.x * blockDim.x + threadIdx.x) * 4;
    if (i + 3 < n) {
        float4 v = *reinterpret_cast<const float4*>(in + i);
        *reinterpret_cast<__half2*>(out + i)     = __floats2half2_rn(v.x, v.y);
        *reinterpret_cast<__half2*>(out + i + 2) = __floats2half2_rn(v.z, v.w);
    }
}

// ---------------- mma.sync GEMM: C[M,N] = A[M,K] @ B[N,K]^T  ------------------
// 512 threads, CTA tile 128x256, warp tile 32x64 (4x4 warps), BK=64, 4 stages.
// EPI=0: C = exp(scale*acc) fp16 ; EPI=1: C = acc * rinv[row] fp32
#define BM 128
#define BN 256
#define BKC 64
#define STAGES 4
#define STG_BYTES ((BM + BN) * 128)          // 48 KB per stage (A then B)
#define SMEM_SZ (STAGES * STG_BYTES)         // 192 KB

template <int EPI>
__global__ __launch_bounds__(512, 1)
void gemm_mma(const __half* __restrict__ A, const __half* __restrict__ B,
              void* __restrict__ Cv, int M, int N, int K,
              const float* __restrict__ rinv) {
    extern __shared__ char smem[];
    const uint32_t sb = smem_u32(smem);
    const int tid = threadIdx.x;
    const int wid = tid >> 5;          // 0..15
    const int lane = tid & 31;
    const int wm = wid & 3;            // 4 warps over M -> 32 rows each
    const int wn = wid >> 2;           // 4 warps over N -> 64 cols each
    const size_t m0 = (size_t)blockIdx.y * BM;
    const size_t n0 = (size_t)blockIdx.x * BN;
    const int nk = K / BKC;

    // cp.async mapping: 8 x 16B chunks per 128B row; 512 threads cover 64 rows/pass
    const int ldrow = tid >> 3;        // 0..63
    const int ldc16 = tid & 7;
    const uint32_t swz_st = ((uint32_t)ldc16 ^ ((uint32_t)ldrow & 7)) << 4;

    auto load_stage = [&](int c, int buf) {
        const uint32_t abase = sb + buf * STG_BYTES;
        const uint32_t bbase = abase + BM * 128;
        const size_t k0 = (size_t)c * BKC;
        #pragma unroll
        for (int i = 0; i < 2; i++) {                  // A: 128 rows
            int row = ldrow + i * 64;
            cp16(abase + row * 128 + swz_st, A + (m0 + row) * (size_t)K + k0 + ldc16 * 8);
        }
        #pragma unroll
        for (int i = 0; i < 4; i++) {                  // B: 256 rows
            int row = ldrow + i * 64;
            cp16(bbase + row * 128 + swz_st, B + (n0 + row) * (size_t)K + k0 + ldc16 * 8);
        }
        asm volatile("cp.async.commit_group;" ::: "memory");
    };

    float acc[2][8][4];
    #pragma unroll
    for (int i = 0; i < 2; i++)
        #pragma unroll
        for (int j = 0; j < 8; j++)
            #pragma unroll
            for (int r = 0; r < 4; r++) acc[i][j][r] = 0.0f;

    #pragma unroll
    for (int s = 0; s < STAGES - 1; s++) load_stage(s, s);

    // ldmatrix lane addressing
    const uint32_t lrow = lane & 15;
    const uint32_t lhalf = lane >> 4;              // 0/1 -> +8 halfs in k
    const uint32_t lswz = lane & 7;
    const uint32_t a_rowbyte = (wm * 32 + lrow) * 128;
    const uint32_t b_rowbyte = (wn * 64 + lrow) * 128;
    uint32_t coff[4];
    #pragma unroll
    for (int k16 = 0; k16 < 4; k16++)
        coff[k16] = (((uint32_t)k16 * 2 + lhalf) ^ lswz) << 4;

    for (int it = 0; it < nk; it++) {
        const int rem = nk - 1 - it;
        if (rem >= 2)      asm volatile("cp.async.wait_group 2;" ::: "memory");
        else if (rem == 1) asm volatile("cp.async.wait_group 1;" ::: "memory");
        else               asm volatile("cp.async.wait_group 0;" ::: "memory");
        __syncthreads();
        if (it + STAGES - 1 < nk) load_stage(it + STAGES - 1, (it + STAGES - 1) % STAGES);

        const uint32_t abase = sb + (it % STAGES) * STG_BYTES;
        const uint32_t bbase = abase + BM * 128;

        #pragma unroll
        for (int k16 = 0; k16 < 4; k16++) {
            uint32_t a[2][4], b[4][4];
            #pragma unroll
            for (int mi = 0; mi < 2; mi++)
                ldsm4(a[mi][0], a[mi][1], a[mi][2], a[mi][3],
                      abase + a_rowbyte + mi * 2048 + coff[k16]);
            #pragma unroll
            for (int ni = 0; ni < 4; ni++)
                ldsm4(b[ni][0], b[ni][1], b[ni][2], b[ni][3],
                      bbase + b_rowbyte + ni * 2048 + coff[k16]);
            #pragma unroll
            for (int mi = 0; mi < 2; mi++)
                #pragma unroll
                for (int nj = 0; nj < 8; nj++)
                    mma16816(acc[mi][nj], a[mi][0], a[mi][1], a[mi][2], a[mi][3],
                             b[nj >> 1][nj & 1], b[nj >> 1][(nj & 1) + 2]);
        }
        // single barrier per iter: with 4 stages the top-of-loop barrier at it+1
        // precedes the load into buffer (it+4)%4 == it%4, protecting iter-it reads
    }

    // ---- epilogue -----------------------------------------------------------
    const float scale = 0.015625f;     // 1/sqrt(4096)
    #pragma unroll
    for (int mi = 0; mi < 2; mi++) {
        const size_t r0 = m0 + wm * 32 + mi * 16 + (lane >> 2);
        const size_t r1 = r0 + 8;
        float i0 = 0.f, i1 = 0.f;
        if (EPI == 1) { i0 = rinv[r0]; i1 = rinv[r1]; }
        #pragma unroll
        for (int nj = 0; nj < 8; nj++) {
            const size_t col = n0 + wn * 64 + nj * 8 + (lane & 3) * 2;
            float* c = acc[mi][nj];
            if (EPI == 0) {
                __half* C = (__half*)Cv;
                *reinterpret_cast<__half2*>(&C[r0 * (size_t)N + col]) =
                    __floats2half2_rn(__expf(c[0] * scale), __expf(c[1] * scale));
                *reinterpret_cast<__half2*>(&C[r1 * (size_t)N + col]) =
                    __floats2half2_rn(__expf(c[2] * scale), __expf(c[3] * scale));
            } else {
                float* C = (float*)Cv;
                *reinterpret_cast<float2*>(&C[r0 * (size_t)N + col]) =
                    make_float2(c[0] * i0, c[1] * i0);
                *reinterpret_cast<float2*>(&C[r1 * (size_t)N + col]) =
                    make_float2(c[2] * i1, c[3] * i1);
            }
        }
    }
}

// ---------------- row sums of P -> reciprocal --------------------------------
__global__ __launch_bounds__(256)
void rowsum_recip(const __half* __restrict__ P, float* __restrict__ rinv, int cols) {
    __shared__ float red[256];
    const int row = blockIdx.x;
    const int tid = threadIdx.x;
    const __half2* p = reinterpret_cast<const __half2*>(P + (size_t)row * cols);
    float s = 0.0f;
    for (int j = tid; j < cols / 2; j += 256) {
        float2 v = __half22float2(p[j]);
        s += v.x + v.y;
    }
    red[tid] = s;
    __syncthreads();
    #pragma unroll
    for (int st = 128; st > 0; st >>= 1) {
        if (tid < st) red[tid] += red[tid + st];
        __syncthreads();
    }
    if (tid == 0) rinv[row] = 1.0f / red[0];
}

// ---------------- launch ------------------------------------------------------
extern "C" void kernel_launch(void* const* d_in, const int* in_sizes, int n_in,
                              void* d_out, int out_size) {
    const float* q = (const float*)d_in[0];   // (4096, 4096)  Q[n][i]
    const float* k = (const float*)d_in[1];   // (4096, 8192)  K[n][j]
    const float* v = (const float*)d_in[2];   // (4096, 8192)  V[v][j]
    float* out = (float*)d_out;               // (4096, 4096)  out[i][v]

    __half *pQt, *pKt, *pVc, *pP;
    float* pRinv;
    cudaGetSymbolAddress((void**)&pQt,   g_Qt);
    cudaGetSymbolAddress((void**)&pKt,   g_Kt);
    cudaGetSymbolAddress((void**)&pVc,   g_Vc);
    cudaGetSymbolAddress((void**)&pP,    g_P);
    cudaGetSymbolAddress((void**)&pRinv, g_rinv);

    cudaFuncSetAttribute(gemm_mma<0>, cudaFuncAttributeMaxDynamicSharedMemorySize, SMEM_SZ);
    cudaFuncSetAttribute(gemm_mma<1>, cudaFuncAttributeMaxDynamicSharedMemorySize, SMEM_SZ);

    dim3 tb(32, 8);
    // Qt[i][n] = Q[n][i]
    transpose_f2h<<<dim3(QDIM / 32, NDIM / 32), tb>>>(q, pQt, NDIM, QDIM);
    // Kt[j][n] = K[n][j]
    transpose_f2h<<<dim3(MDIM / 32, NDIM / 32), tb>>>(k, pKt, NDIM, MDIM);
    // Vc straight convert
    {
        size_t n = (size_t)VDIM * MDIM;
        convert_f2h<<<(unsigned)(n / 4 / 256), 256>>>(v, pVc, n);
    }

    // GEMM1 + fused exp: P[i][j] = exp(scale * sum_n Qt[i][n] Kt[j][n])
    gemm_mma<0><<<dim3(MDIM / BN, QDIM / BM), 512, SMEM_SZ>>>(
        pQt, pKt, pP, QDIM, MDIM, NDIM, nullptr);

    // row sums -> reciprocals
    rowsum_recip<<<QDIM, 256>>>(pP, pRinv, MDIM);

    // GEMM2 + fused normalize: out[i][v] = rinv[i] * sum_j P[i][j] Vc[v][j]
    gemm_mma<1><<<dim3(VDIM / BN, QDIM / BM), 512, SMEM_SZ>>>(
        pP, pVc, out, QDIM, VDIM, MDIM, pRinv);
}

// round 8
// speedup vs baseline: 1.1071x; 1.0472x over previous
#include <cuda_runtime.h>
#include <cuda_fp16.h>
#include <cstdint>

#define QDIM 4096   // q_dim (output rows i)
#define NDIM 4096   // contraction of GEMM1 (n)
#define MDIM 8192   // softmax dim / contraction of GEMM2 (j)
#define VDIM 4096   // v_dim (output cols v)

// ---------------- scratch (static device globals) ---------------------------
__device__ __half g_Qt[(size_t)QDIM * NDIM];   // Qt[i][n] = Q[n][i]
__device__ __half g_Kt[(size_t)MDIM * NDIM];   // Kt[j][n] = K[n][j]
__device__ __half g_Vc[(size_t)VDIM * MDIM];   // Vc[v][j] = V[v][j]
__device__ __half g_P [(size_t)QDIM * MDIM];   // exp(s) UNNORMALIZED fp16
__device__ float  g_rinv[QDIM];                // 1 / row sums

// ---------------- helpers ----------------------------------------------------
__device__ __forceinline__ uint32_t smem_u32(const void* p) {
    uint32_t a;
    asm("{ .reg .u64 t; cvta.to.shared.u64 t, %1; cvt.u32.u64 %0, t; }" : "=r"(a) : "l"(p));
    return a;
}
__device__ __forceinline__ void cp16(uint32_t dst, const void* src) {
    asm volatile("cp.async.cg.shared.global [%0], [%1], 16;" :: "r"(dst), "l"(src));
}
__device__ __forceinline__ void ldsm4(uint32_t& r0, uint32_t& r1, uint32_t& r2, uint32_t& r3,
                                      uint32_t addr) {
    asm volatile("ldmatrix.sync.aligned.m8n8.x4.shared.b16 {%0,%1,%2,%3}, [%4];"
                 : "=r"(r0), "=r"(r1), "=r"(r2), "=r"(r3) : "r"(addr));
}
__device__ __forceinline__ void mma16816(float* d, uint32_t a0, uint32_t a1, uint32_t a2,
                                         uint32_t a3, uint32_t b0, uint32_t b1) {
    asm volatile(
        "mma.sync.aligned.m16n8k16.row.col.f32.f16.f16.f32 "
        "{%0,%1,%2,%3}, {%4,%5,%6,%7}, {%8,%9}, {%0,%1,%2,%3};"
        : "+f"(d[0]), "+f"(d[1]), "+f"(d[2]), "+f"(d[3])
        : "r"(a0), "r"(a1), "r"(a2), "r"(a3), "r"(b0), "r"(b1));
}

// ---------------- preprocessing (R3 known-good versions) ----------------------
__global__ void transpose_f2h(const float* __restrict__ in, __half* __restrict__ out,
                              int rows, int cols) {
    __shared__ float tile[32][33];
    int c0 = blockIdx.x * 32, r0 = blockIdx.y * 32;
    int tx = threadIdx.x, ty = threadIdx.y;
    #pragma unroll
    for (int i = ty; i < 32; i += 8)
        tile[i][tx] = in[(size_t)(r0 + i) * cols + (c0 + tx)];
    __syncthreads();
    #pragma unroll
    for (int i = ty; i < 32; i += 8)
        out[(size_t)(c0 + i) * rows + (r0 + tx)] = __float2half(tile[tx][i]);
}

__global__ void convert_f2h(const float* __restrict__ in, __half* __restrict__ out, size_t n) {
    size_t i = ((size_t)blockIdx.x * blockDim.x + threadIdx.x) * 4;
    if (i + 3 < n) {
        float4 v = *reinterpret_cast<const float4*>(in + i);
        *reinterpret_cast<__half2*>(out + i)     = __floats2half2_rn(v.x, v.y);
        *reinterpret_cast<__half2*>(out + i + 2) = __floats2half2_rn(v.z, v.w);
    }
}

// =============================================================================
// GEMM1 (R7 config): 512 thr, tile 128x256, warp 32x64, 4 stages, 1 CTA/SM.
// C = exp(scale*acc) fp16 (unnormalized softmax numerator)
// =============================================================================
#define BM1 128
#define BN1 256
#define BKC 64
#define STAGES1 4
#define STG1_BYTES ((BM1 + BN1) * 128)        // 48 KB
#define SMEM1_SZ (STAGES1 * STG1_BYTES)       // 192 KB

__global__ __launch_bounds__(512, 1)
void gemm1_mma(const __half* __restrict__ A, const __half* __restrict__ B,
               __half* __restrict__ C, int M, int N, int K) {
    extern __shared__ char smem[];
    const uint32_t sb = smem_u32(smem);
    const int tid = threadIdx.x;
    const int wid = tid >> 5;          // 0..15
    const int lane = tid & 31;
    const int wm = wid & 3;            // 4 warps over M -> 32 rows each
    const int wn = wid >> 2;           // 4 warps over N -> 64 cols each
    const size_t m0 = (size_t)blockIdx.y * BM1;
    const size_t n0 = (size_t)blockIdx.x * BN1;
    const int nk = K / BKC;

    const int ldrow = tid >> 3;        // 0..63
    const int ldc16 = tid & 7;
    const uint32_t swz_st = ((uint32_t)ldc16 ^ ((uint32_t)ldrow & 7)) << 4;

    auto load_stage = [&](int c, int buf) {
        const uint32_t abase = sb + buf * STG1_BYTES;
        const uint32_t bbase = abase + BM1 * 128;
        const size_t k0 = (size_t)c * BKC;
        #pragma unroll
        for (int i = 0; i < 2; i++) {
            int row = ldrow + i * 64;
            cp16(abase + row * 128 + swz_st, A + (m0 + row) * (size_t)K + k0 + ldc16 * 8);
        }
        #pragma unroll
        for (int i = 0; i < 4; i++) {
            int row = ldrow + i * 64;
            cp16(bbase + row * 128 + swz_st, B + (n0 + row) * (size_t)K + k0 + ldc16 * 8);
        }
        asm volatile("cp.async.commit_group;" ::: "memory");
    };

    float acc[2][8][4];
    #pragma unroll
    for (int i = 0; i < 2; i++)
        #pragma unroll
        for (int j = 0; j < 8; j++)
            #pragma unroll
            for (int r = 0; r < 4; r++) acc[i][j][r] = 0.0f;

    #pragma unroll
    for (int s = 0; s < STAGES1 - 1; s++) load_stage(s, s);

    const uint32_t lrow = lane & 15;
    const uint32_t lhalf = lane >> 4;
    const uint32_t lswz = lane & 7;
    const uint32_t a_rowbyte = (wm * 32 + lrow) * 128;
    const uint32_t b_rowbyte = (wn * 64 + lrow) * 128;
    uint32_t coff[4];
    #pragma unroll
    for (int k16 = 0; k16 < 4; k16++)
        coff[k16] = (((uint32_t)k16 * 2 + lhalf) ^ lswz) << 4;

    for (int it = 0; it < nk; it++) {
        const int rem = nk - 1 - it;
        if (rem >= 2)      asm volatile("cp.async.wait_group 2;" ::: "memory");
        else if (rem == 1) asm volatile("cp.async.wait_group 1;" ::: "memory");
        else               asm volatile("cp.async.wait_group 0;" ::: "memory");
        __syncthreads();
        if (it + STAGES1 - 1 < nk) load_stage(it + STAGES1 - 1, (it + STAGES1 - 1) % STAGES1);

        const uint32_t abase = sb + (it % STAGES1) * STG1_BYTES;
        const uint32_t bbase = abase + BM1 * 128;

        #pragma unroll
        for (int k16 = 0; k16 < 4; k16++) {
            uint32_t a[2][4], b[4][4];
            #pragma unroll
            for (int mi = 0; mi < 2; mi++)
                ldsm4(a[mi][0], a[mi][1], a[mi][2], a[mi][3],
                      abase + a_rowbyte + mi * 2048 + coff[k16]);
            #pragma unroll
            for (int ni = 0; ni < 4; ni++)
                ldsm4(b[ni][0], b[ni][1], b[ni][2], b[ni][3],
                      bbase + b_rowbyte + ni * 2048 + coff[k16]);
            #pragma unroll
            for (int mi = 0; mi < 2; mi++)
                #pragma unroll
                for (int nj = 0; nj < 8; nj++)
                    mma16816(acc[mi][nj], a[mi][0], a[mi][1], a[mi][2], a[mi][3],
                             b[nj >> 1][nj & 1], b[nj >> 1][(nj & 1) + 2]);
        }
    }

    const float scale = 0.015625f;     // 1/sqrt(4096)
    #pragma unroll
    for (int mi = 0; mi < 2; mi++) {
        const size_t r0 = m0 + wm * 32 + mi * 16 + (lane >> 2);
        const size_t r1 = r0 + 8;
        #pragma unroll
        for (int nj = 0; nj < 8; nj++) {
            const size_t col = n0 + wn * 64 + nj * 8 + (lane & 3) * 2;
            float* c = acc[mi][nj];
            *reinterpret_cast<__half2*>(&C[r0 * (size_t)N + col]) =
                __floats2half2_rn(__expf(c[0] * scale), __expf(c[1] * scale));
            *reinterpret_cast<__half2*>(&C[r1 * (size_t)N + col]) =
                __floats2half2_rn(__expf(c[2] * scale), __expf(c[3] * scale));
        }
    }
}

// =============================================================================
// GEMM2 (R3 config): 256 thr, tile 128x128, warp 64x32, 3 stages, 2 CTAs/SM.
// C = acc * rinv[row] fp32
// =============================================================================
#define BM2 128
#define BN2 128
#define STAGES2 3
#define STG2_BYTES ((BM2 + BN2) * 128)        // 32 KB
#define SMEM2_SZ (STAGES2 * STG2_BYTES)       // 96 KB

__global__ __launch_bounds__(256, 2)
void gemm2_mma(const __half* __restrict__ A, const __half* __restrict__ B,
               float* __restrict__ C, int M, int N, int K,
               const float* __restrict__ rinv) {
    extern __shared__ char smem[];
    const uint32_t sb = smem_u32(smem);
    const int tid = threadIdx.x;
    const int wid = tid >> 5;
    const int lane = tid & 31;
    const int wm = wid & 1;           // 2 warps over M -> 64 rows each
    const int wn = wid >> 1;          // 4 warps over N -> 32 cols each
    const size_t m0 = (size_t)blockIdx.y * BM2;
    const size_t n0 = (size_t)blockIdx.x * BN2;
    const int nk = K / BKC;

    const int ldrow = tid >> 3;          // 0..31
    const int ldc16 = tid & 7;
    const uint32_t swz_st = ((uint32_t)ldc16 ^ ((uint32_t)ldrow & 7)) << 4;

    auto load_stage = [&](int c, int buf) {
        const uint32_t abase = sb + buf * STG2_BYTES;
        const uint32_t bbase = abase + BM2 * 128;
        const size_t k0 = (size_t)c * BKC;
        #pragma unroll
        for (int i = 0; i < 4; i++) {
            int row = ldrow + i * 32;
            cp16(abase + row * 128 + swz_st, A + (m0 + row) * (size_t)K + k0 + ldc16 * 8);
        }
        #pragma unroll
        for (int i = 0; i < 4; i++) {
            int row = ldrow + i * 32;
            cp16(bbase + row * 128 + swz_st, B + (n0 + row) * (size_t)K + k0 + ldc16 * 8);
        }
        asm volatile("cp.async.commit_group;" ::: "memory");
    };

    float acc[4][4][4];
    #pragma unroll
    for (int i = 0; i < 4; i++)
        #pragma unroll
        for (int j = 0; j < 4; j++)
            #pragma unroll
            for (int r = 0; r < 4; r++) acc[i][j][r] = 0.0f;

    #pragma unroll
    for (int s = 0; s < STAGES2 - 1; s++) load_stage(s, s);

    const uint32_t lrow = lane & 15;
    const uint32_t lhalf = lane >> 4;
    const uint32_t lswz = lane & 7;
    const uint32_t a_rowbyte = (wm * 64 + lrow) * 128;
    const uint32_t b_rowbyte = (wn * 32 + lrow) * 128;

    for (int it = 0; it < nk; it++) {
        asm volatile("cp.async.wait_group %0;" :: "n"(STAGES2 - 2) : "memory");
        __syncthreads();
        if (it + STAGES2 - 1 < nk) load_stage(it + STAGES2 - 1, (it + STAGES2 - 1) % STAGES2);

        const uint32_t abase = sb + (it % STAGES2) * STG2_BYTES;
        const uint32_t bbase = abase + BM2 * 128;

        #pragma unroll
        for (int k16 = 0; k16 < 4; k16++) {
            const uint32_t c16 = (uint32_t)k16 * 2 + lhalf;
            const uint32_t coff = ((c16 ^ lswz) << 4);
            uint32_t a[4][4], b[2][4];
            #pragma unroll
            for (int mi = 0; mi < 4; mi++)
                ldsm4(a[mi][0], a[mi][1], a[mi][2], a[mi][3],
                      abase + a_rowbyte + mi * 2048 + coff);
            #pragma unroll
            for (int ni = 0; ni < 2; ni++)
                ldsm4(b[ni][0], b[ni][1], b[ni][2], b[ni][3],
                      bbase + b_rowbyte + ni * 2048 + coff);
            #pragma unroll
            for (int mi = 0; mi < 4; mi++)
                #pragma unroll
                for (int nj = 0; nj < 4; nj++)
                    mma16816(acc[mi][nj], a[mi][0], a[mi][1], a[mi][2], a[mi][3],
                             b[nj >> 1][nj & 1], b[nj >> 1][(nj & 1) + 2]);
        }
        __syncthreads();
    }

    #pragma unroll
    for (int mi = 0; mi < 4; mi++) {
        const size_t r0 = m0 + wm * 64 + mi * 16 + (lane >> 2);
        const size_t r1 = r0 + 8;
        const float i0 = rinv[r0];
        const float i1 = rinv[r1];
        #pragma unroll
        for (int nj = 0; nj < 4; nj++) {
            const size_t col = n0 + wn * 32 + nj * 8 + (lane & 3) * 2;
            float* c = acc[mi][nj];
            *reinterpret_cast<float2*>(&C[r0 * (size_t)N + col]) =
                make_float2(c[0] * i0, c[1] * i0);
            *reinterpret_cast<float2*>(&C[r1 * (size_t)N + col]) =
                make_float2(c[2] * i1, c[3] * i1);
        }
    }
}

// ---------------- row sums of P -> reciprocal --------------------------------
__global__ __launch_bounds__(256)
void rowsum_recip(const __half* __restrict__ P, float* __restrict__ rinv, int cols) {
    __shared__ float red[256];
    const int row = blockIdx.x;
    const int tid = threadIdx.x;
    const __half2* p = reinterpret_cast<const __half2*>(P + (size_t)row * cols);
    float s = 0.0f;
    for (int j = tid; j < cols / 2; j += 256) {
        float2 v = __half22float2(p[j]);
        s += v.x + v.y;
    }
    red[tid] = s;
    __syncthreads();
    #pragma unroll
    for (int st = 128; st > 0; st >>= 1) {
        if (tid < st) red[tid] += red[tid + st];
        __syncthreads();
    }
    if (tid == 0) rinv[row] = 1.0f / red[0];
}

// ---------------- launch ------------------------------------------------------
extern "C" void kernel_launch(void* const* d_in, const int* in_sizes, int n_in,
                              void* d_out, int out_size) {
    const float* q = (const float*)d_in[0];   // (4096, 4096)  Q[n][i]
    const float* k = (const float*)d_in[1];   // (4096, 8192)  K[n][j]
    const float* v = (const float*)d_in[2];   // (4096, 8192)  V[v][j]
    float* out = (float*)d_out;               // (4096, 4096)  out[i][v]

    __half *pQt, *pKt, *pVc, *pP;
    float* pRinv;
    cudaGetSymbolAddress((void**)&pQt,   g_Qt);
    cudaGetSymbolAddress((void**)&pKt,   g_Kt);
    cudaGetSymbolAddress((void**)&pVc,   g_Vc);
    cudaGetSymbolAddress((void**)&pP,    g_P);
    cudaGetSymbolAddress((void**)&pRinv, g_rinv);

    cudaFuncSetAttribute(gemm1_mma, cudaFuncAttributeMaxDynamicSharedMemorySize, SMEM1_SZ);
    cudaFuncSetAttribute(gemm2_mma, cudaFuncAttributeMaxDynamicSharedMemorySize, SMEM2_SZ);

    dim3 tb(32, 8);
    // Qt[i][n] = Q[n][i]
    transpose_f2h<<<dim3(QDIM / 32, NDIM / 32), tb>>>(q, pQt, NDIM, QDIM);
    // Kt[j][n] = K[n][j]
    transpose_f2h<<<dim3(MDIM / 32, NDIM / 32), tb>>>(k, pKt, NDIM, MDIM);
    // Vc straight convert
    {
        size_t n = (size_t)VDIM * MDIM;
        convert_f2h<<<(unsigned)(n / 4 / 256), 256>>>(v, pVc, n);
    }

    // GEMM1 + fused exp: P[i][j] = exp(scale * sum_n Qt[i][n] Kt[j][n])
    gemm1_mma<<<dim3(MDIM / BN1, QDIM / BM1), 512, SMEM1_SZ>>>(
        pQt, pKt, pP, QDIM, MDIM, NDIM);

    // row sums -> reciprocals
    rowsum_recip<<<QDIM, 256>>>(pP, pRinv, MDIM);

    // GEMM2 + fused normalize: out[i][v] = rinv[i] * sum_j P[i][j] Vc[v][j]
    gemm2_mma<<<dim3(VDIM / BN2, QDIM / BM2), 256, SMEM2_SZ>>>(
        pP, pVc, out, QDIM, VDIM, MDIM, pRinv);
}

// round 9
// speedup vs baseline: 1.1136x; 1.0058x over previous
#include <cuda_runtime.h>
#include <cuda_fp16.h>
#include <cstdint>

#define QDIM 4096   // q_dim (output rows i)
#define NDIM 4096   // contraction of GEMM1 (n)
#define MDIM 8192   // softmax dim / contraction of GEMM2 (j)
#define VDIM 4096   // v_dim (output cols v)

// ---------------- scratch (static device globals) ---------------------------
__device__ __half g_Qt[(size_t)QDIM * NDIM];   // Qt[i][n] = Q[n][i]
__device__ __half g_Kt[(size_t)MDIM * NDIM];   // Kt[j][n] = K[n][j]
__device__ __half g_Vc[(size_t)VDIM * MDIM];   // Vc[v][j] = V[v][j]
__device__ __half g_P [(size_t)QDIM * MDIM];   // exp(s) UNNORMALIZED fp16
__device__ float  g_rinv[QDIM];                // 1 / row sums

// ---------------- helpers ----------------------------------------------------
__device__ __forceinline__ uint32_t smem_u32(const void* p) {
    uint32_t a;
    asm("{ .reg .u64 t; cvta.to.shared.u64 t, %1; cvt.u32.u64 %0, t; }" : "=r"(a) : "l"(p));
    return a;
}
__device__ __forceinline__ void cp16(uint32_t dst, const void* src) {
    asm volatile("cp.async.cg.shared.global [%0], [%1], 16;" :: "r"(dst), "l"(src));
}
__device__ __forceinline__ void ldsm4(uint32_t& r0, uint32_t& r1, uint32_t& r2, uint32_t& r3,
                                      uint32_t addr) {
    asm volatile("ldmatrix.sync.aligned.m8n8.x4.shared.b16 {%0,%1,%2,%3}, [%4];"
                 : "=r"(r0), "=r"(r1), "=r"(r2), "=r"(r3) : "r"(addr));
}
__device__ __forceinline__ void mma16816(float* d, uint32_t a0, uint32_t a1, uint32_t a2,
                                         uint32_t a3, uint32_t b0, uint32_t b1) {
    asm volatile(
        "mma.sync.aligned.m16n8k16.row.col.f32.f16.f16.f32 "
        "{%0,%1,%2,%3}, {%4,%5,%6,%7}, {%8,%9}, {%0,%1,%2,%3};"
        : "+f"(d[0]), "+f"(d[1]), "+f"(d[2]), "+f"(d[3])
        : "r"(a0), "r"(a1), "r"(a2), "r"(a3), "r"(b0), "r"(b1));
}

// ---------------- preprocessing (known-good versions) -------------------------
__global__ void transpose_f2h(const float* __restrict__ in, __half* __restrict__ out,
                              int rows, int cols) {
    __shared__ float tile[32][33];
    int c0 = blockIdx.x * 32, r0 = blockIdx.y * 32;
    int tx = threadIdx.x, ty = threadIdx.y;
    #pragma unroll
    for (int i = ty; i < 32; i += 8)
        tile[i][tx] = in[(size_t)(r0 + i) * cols + (c0 + tx)];
    __syncthreads();
    #pragma unroll
    for (int i = ty; i < 32; i += 8)
        out[(size_t)(c0 + i) * rows + (r0 + tx)] = __float2half(tile[tx][i]);
}

__global__ void convert_f2h(const float* __restrict__ in, __half* __restrict__ out, size_t n) {
    size_t i = ((size_t)blockIdx.x * blockDim.x + threadIdx.x) * 4;
    if (i + 3 < n) {
        float4 v = *reinterpret_cast<const float4*>(in + i);
        *reinterpret_cast<__half2*>(out + i)     = __floats2half2_rn(v.x, v.y);
        *reinterpret_cast<__half2*>(out + i + 2) = __floats2half2_rn(v.z, v.w);
    }
}

// =============================================================================
// GEMM1 (R7/R8 config, measured 718us): 512 thr, 128x256, warp 32x64, 4 stages.
// C = exp(scale*acc) fp16
// =============================================================================
#define BM1 128
#define BN1 256
#define BKC 64
#define STAGES1 4
#define STG1_BYTES ((BM1 + BN1) * 128)        // 48 KB
#define SMEM1_SZ (STAGES1 * STG1_BYTES)       // 192 KB

__global__ __launch_bounds__(512, 1)
void gemm1_mma(const __half* __restrict__ A, const __half* __restrict__ B,
               __half* __restrict__ C, int M, int N, int K) {
    extern __shared__ char smem[];
    const uint32_t sb = smem_u32(smem);
    const int tid = threadIdx.x;
    const int wid = tid >> 5;
    const int lane = tid & 31;
    const int wm = wid & 3;            // 4 warps over M -> 32 rows
    const int wn = wid >> 2;           // 4 warps over N -> 64 cols
    const size_t m0 = (size_t)blockIdx.y * BM1;
    const size_t n0 = (size_t)blockIdx.x * BN1;
    const int nk = K / BKC;

    const int ldrow = tid >> 3;
    const int ldc16 = tid & 7;
    const uint32_t swz_st = ((uint32_t)ldc16 ^ ((uint32_t)ldrow & 7)) << 4;

    auto load_stage = [&](int c, int buf) {
        const uint32_t abase = sb + buf * STG1_BYTES;
        const uint32_t bbase = abase + BM1 * 128;
        const size_t k0 = (size_t)c * BKC;
        #pragma unroll
        for (int i = 0; i < 2; i++) {
            int row = ldrow + i * 64;
            cp16(abase + row * 128 + swz_st, A + (m0 + row) * (size_t)K + k0 + ldc16 * 8);
        }
        #pragma unroll
        for (int i = 0; i < 4; i++) {
            int row = ldrow + i * 64;
            cp16(bbase + row * 128 + swz_st, B + (n0 + row) * (size_t)K + k0 + ldc16 * 8);
        }
        asm volatile("cp.async.commit_group;" ::: "memory");
    };

    float acc[2][8][4];
    #pragma unroll
    for (int i = 0; i < 2; i++)
        #pragma unroll
        for (int j = 0; j < 8; j++)
            #pragma unroll
            for (int r = 0; r < 4; r++) acc[i][j][r] = 0.0f;

    #pragma unroll
    for (int s = 0; s < STAGES1 - 1; s++) load_stage(s, s);

    const uint32_t lrow = lane & 15;
    const uint32_t lhalf = lane >> 4;
    const uint32_t lswz = lane & 7;
    const uint32_t a_rowbyte = (wm * 32 + lrow) * 128;
    const uint32_t b_rowbyte = (wn * 64 + lrow) * 128;
    uint32_t coff[4];
    #pragma unroll
    for (int k16 = 0; k16 < 4; k16++)
        coff[k16] = (((uint32_t)k16 * 2 + lhalf) ^ lswz) << 4;

    for (int it = 0; it < nk; it++) {
        const int rem = nk - 1 - it;
        if (rem >= 2)      asm volatile("cp.async.wait_group 2;" ::: "memory");
        else if (rem == 1) asm volatile("cp.async.wait_group 1;" ::: "memory");
        else               asm volatile("cp.async.wait_group 0;" ::: "memory");
        __syncthreads();
        if (it + STAGES1 - 1 < nk) load_stage(it + STAGES1 - 1, (it + STAGES1 - 1) % STAGES1);

        const uint32_t abase = sb + (it % STAGES1) * STG1_BYTES;
        const uint32_t bbase = abase + BM1 * 128;

        #pragma unroll
        for (int k16 = 0; k16 < 4; k16++) {
            uint32_t a[2][4], b[4][4];
            #pragma unroll
            for (int mi = 0; mi < 2; mi++)
                ldsm4(a[mi][0], a[mi][1], a[mi][2], a[mi][3],
                      abase + a_rowbyte + mi * 2048 + coff[k16]);
            #pragma unroll
            for (int ni = 0; ni < 4; ni++)
                ldsm4(b[ni][0], b[ni][1], b[ni][2], b[ni][3],
                      bbase + b_rowbyte + ni * 2048 + coff[k16]);
            #pragma unroll
            for (int mi = 0; mi < 2; mi++)
                #pragma unroll
                for (int nj = 0; nj < 8; nj++)
                    mma16816(acc[mi][nj], a[mi][0], a[mi][1], a[mi][2], a[mi][3],
                             b[nj >> 1][nj & 1], b[nj >> 1][(nj & 1) + 2]);
        }
    }

    const float scale = 0.015625f;     // 1/sqrt(4096)
    #pragma unroll
    for (int mi = 0; mi < 2; mi++) {
        const size_t r0 = m0 + wm * 32 + mi * 16 + (lane >> 2);
        const size_t r1 = r0 + 8;
        #pragma unroll
        for (int nj = 0; nj < 8; nj++) {
            const size_t col = n0 + wn * 64 + nj * 8 + (lane & 3) * 2;
            float* c = acc[mi][nj];
            *reinterpret_cast<__half2*>(&C[r0 * (size_t)N + col]) =
                __floats2half2_rn(__expf(c[0] * scale), __expf(c[1] * scale));
            *reinterpret_cast<__half2*>(&C[r1 * (size_t)N + col]) =
                __floats2half2_rn(__expf(c[2] * scale), __expf(c[3] * scale));
        }
    }
}

// =============================================================================
// GEMM2 (new): 512 thr, tile 128x128, warp 32x32 (4x4), 3 stages, 2 CTAs/SM.
// 32 warps/SM. C = acc * rinv[row] fp32
// =============================================================================
#define BM2 128
#define BN2 128
#define STAGES2 3
#define STG2_BYTES ((BM2 + BN2) * 128)        // 32 KB
#define SMEM2_SZ (STAGES2 * STG2_BYTES)       // 96 KB

__global__ __launch_bounds__(512, 2)
void gemm2_mma(const __half* __restrict__ A, const __half* __restrict__ B,
               float* __restrict__ C, int M, int N, int K,
               const float* __restrict__ rinv) {
    extern __shared__ char smem[];
    const uint32_t sb = smem_u32(smem);
    const int tid = threadIdx.x;
    const int wid = tid >> 5;          // 0..15
    const int lane = tid & 31;
    const int wm = wid & 3;            // 4 warps over M -> 32 rows
    const int wn = wid >> 2;           // 4 warps over N -> 32 cols
    const size_t m0 = (size_t)blockIdx.y * BM2;
    const size_t n0 = (size_t)blockIdx.x * BN2;
    const int nk = K / BKC;

    const int ldrow = tid >> 3;        // 0..63
    const int ldc16 = tid & 7;
    const uint32_t swz_st = ((uint32_t)ldc16 ^ ((uint32_t)ldrow & 7)) << 4;

    auto load_stage = [&](int c, int buf) {
        const uint32_t abase = sb + buf * STG2_BYTES;
        const uint32_t bbase = abase + BM2 * 128;
        const size_t k0 = (size_t)c * BKC;
        #pragma unroll
        for (int i = 0; i < 2; i++) {                  // A: 128 rows
            int row = ldrow + i * 64;
            cp16(abase + row * 128 + swz_st, A + (m0 + row) * (size_t)K + k0 + ldc16 * 8);
        }
        #pragma unroll
        for (int i = 0; i < 2; i++) {                  // B: 128 rows
            int row = ldrow + i * 64;
            cp16(bbase + row * 128 + swz_st, B + (n0 + row) * (size_t)K + k0 + ldc16 * 8);
        }
        asm volatile("cp.async.commit_group;" ::: "memory");
    };

    float acc[2][4][4];
    #pragma unroll
    for (int i = 0; i < 2; i++)
        #pragma unroll
        for (int j = 0; j < 4; j++)
            #pragma unroll
            for (int r = 0; r < 4; r++) acc[i][j][r] = 0.0f;

    #pragma unroll
    for (int s = 0; s < STAGES2 - 1; s++) load_stage(s, s);

    const uint32_t lrow = lane & 15;
    const uint32_t lhalf = lane >> 4;
    const uint32_t lswz = lane & 7;
    const uint32_t a_rowbyte = (wm * 32 + lrow) * 128;
    const uint32_t b_rowbyte = (wn * 32 + lrow) * 128;
    uint32_t coff[4];
    #pragma unroll
    for (int k16 = 0; k16 < 4; k16++)
        coff[k16] = (((uint32_t)k16 * 2 + lhalf) ^ lswz) << 4;

    for (int it = 0; it < nk; it++) {
        if (it + 1 < nk) asm volatile("cp.async.wait_group 1;" ::: "memory");
        else             asm volatile("cp.async.wait_group 0;" ::: "memory");
        __syncthreads();
        if (it + STAGES2 - 1 < nk) load_stage(it + STAGES2 - 1, (it + STAGES2 - 1) % STAGES2);

        const uint32_t abase = sb + (it % STAGES2) * STG2_BYTES;
        const uint32_t bbase = abase + BM2 * 128;

        #pragma unroll
        for (int k16 = 0; k16 < 4; k16++) {
            uint32_t a[2][4], b[2][4];
            #pragma unroll
            for (int mi = 0; mi < 2; mi++)
                ldsm4(a[mi][0], a[mi][1], a[mi][2], a[mi][3],
                      abase + a_rowbyte + mi * 2048 + coff[k16]);
            #pragma unroll
            for (int ni = 0; ni < 2; ni++)
                ldsm4(b[ni][0], b[ni][1], b[ni][2], b[ni][3],
                      bbase + b_rowbyte + ni * 2048 + coff[k16]);
            #pragma unroll
            for (int mi = 0; mi < 2; mi++)
                #pragma unroll
                for (int nj = 0; nj < 4; nj++)
                    mma16816(acc[mi][nj], a[mi][0], a[mi][1], a[mi][2], a[mi][3],
                             b[nj >> 1][nj & 1], b[nj >> 1][(nj & 1) + 2]);
        }
        // single barrier per iter (3 stages): top barrier at it+1 precedes the
        // load into buffer (it+3)%3 == it%3, protecting iter-it's reads
    }

    #pragma unroll
    for (int mi = 0; mi < 2; mi++) {
        const size_t r0 = m0 + wm * 32 + mi * 16 + (lane >> 2);
        const size_t r1 = r0 + 8;
        const float i0 = rinv[r0];
        const float i1 = rinv[r1];
        #pragma unroll
        for (int nj = 0; nj < 4; nj++) {
            const size_t col = n0 + wn * 32 + nj * 8 + (lane & 3) * 2;
            float* c = acc[mi][nj];
            *reinterpret_cast<float2*>(&C[r0 * (size_t)N + col]) =
                make_float2(c[0] * i0, c[1] * i0);
            *reinterpret_cast<float2*>(&C[r1 * (size_t)N + col]) =
                make_float2(c[2] * i1, c[3] * i1);
        }
    }
}

// ---------------- row sums of P -> reciprocal --------------------------------
__global__ __launch_bounds__(256)
void rowsum_recip(const __half* __restrict__ P, float* __restrict__ rinv, int cols) {
    __shared__ float red[256];
    const int row = blockIdx.x;
    const int tid = threadIdx.x;
    const __half2* p = reinterpret_cast<const __half2*>(P + (size_t)row * cols);
    float s = 0.0f;
    for (int j = tid; j < cols / 2; j += 256) {
        float2 v = __half22float2(p[j]);
        s += v.x + v.y;
    }
    red[tid] = s;
    __syncthreads();
    #pragma unroll
    for (int st = 128; st > 0; st >>= 1) {
        if (tid < st) red[tid] += red[tid + st];
        __syncthreads();
    }
    if (tid == 0) rinv[row] = 1.0f / red[0];
}

// ---------------- launch ------------------------------------------------------
extern "C" void kernel_launch(void* const* d_in, const int* in_sizes, int n_in,
                              void* d_out, int out_size) {
    const float* q = (const float*)d_in[0];   // (4096, 4096)  Q[n][i]
    const float* k = (const float*)d_in[1];   // (4096, 8192)  K[n][j]
    const float* v = (const float*)d_in[2];   // (4096, 8192)  V[v][j]
    float* out = (float*)d_out;               // (4096, 4096)  out[i][v]

    __half *pQt, *pKt, *pVc, *pP;
    float* pRinv;
    cudaGetSymbolAddress((void**)&pQt,   g_Qt);
    cudaGetSymbolAddress((void**)&pKt,   g_Kt);
    cudaGetSymbolAddress((void**)&pVc,   g_Vc);
    cudaGetSymbolAddress((void**)&pP,    g_P);
    cudaGetSymbolAddress((void**)&pRinv, g_rinv);

    cudaFuncSetAttribute(gemm1_mma, cudaFuncAttributeMaxDynamicSharedMemorySize, SMEM1_SZ);
    cudaFuncSetAttribute(gemm2_mma, cudaFuncAttributeMaxDynamicSharedMemorySize, SMEM2_SZ);

    dim3 tb(32, 8);
    // Qt[i][n] = Q[n][i]
    transpose_f2h<<<dim3(QDIM / 32, NDIM / 32), tb>>>(q, pQt, NDIM, QDIM);
    // Kt[j][n] = K[n][j]
    transpose_f2h<<<dim3(MDIM / 32, NDIM / 32), tb>>>(k, pKt, NDIM, MDIM);
    // Vc straight convert
    {
        size_t n = (size_t)VDIM * MDIM;
        convert_f2h<<<(unsigned)(n / 4 / 256), 256>>>(v, pVc, n);
    }

    // GEMM1 + fused exp: P[i][j] = exp(scale * sum_n Qt[i][n] Kt[j][n])
    gemm1_mma<<<dim3(MDIM / BN1, QDIM / BM1), 512, SMEM1_SZ>>>(
        pQt, pKt, pP, QDIM, MDIM, NDIM);

    // row sums -> reciprocals
    rowsum_recip<<<QDIM, 256>>>(pP, pRinv, MDIM);

    // GEMM2 + fused normalize: out[i][v] = rinv[i] * sum_j P[i][j] Vc[v][j]
    gemm2_mma<<<dim3(VDIM / BN2, QDIM / BM2), 512, SMEM2_SZ>>>(
        pP, pVc, out, QDIM, VDIM, MDIM, pRinv);
}